// round 8
// baseline (speedup 1.0000x reference)
#include <cuda_runtime.h>
#include <cuda_bf16.h>

typedef unsigned long long ull;

#define DI static __device__ __forceinline__

// ---- packed f32x2 helpers (sm_100a) ----
DI ull ffma2(ull a, ull b, ull c) {
    ull d;
    asm("fma.rn.f32x2 %0, %1, %2, %3;" : "=l"(d) : "l"(a), "l"(b), "l"(c));
    return d;
}
DI ull fmul2(ull a, ull b) {
    ull d;
    asm("mul.rn.f32x2 %0, %1, %2;" : "=l"(d) : "l"(a), "l"(b));
    return d;
}
DI ull pack2(float lo, float hi) {
    ull d;
    asm("mov.b64 %0, {%1, %2};" : "=l"(d) : "f"(lo), "f"(hi));
    return d;
}
DI float2 unpack2(ull v) {
    float2 r;
    asm("mov.b64 {%0, %1}, %2;" : "=f"(r.x), "=f"(r.y) : "l"(v));
    return r;
}

constexpr int B = 2, T = 1024, D = 768, S = 128, HALF = 24;
constexpr int ROWS = B * D;            // 1536
constexpr int KSPLIT = 3, KSEG = 256;  // 3 * 256 = 768 = K

// ---- device scratch (static: no allocation) ----
__device__ float g_xp[KSPLIT * ROWS * T];   // K-split partials of x@M, (row,t)

// ============================================================
// GEMM: xp[ks][b*768+c][t] = sum_{k in seg ks} M[k,c] * x[b,t,k]
// 128(c) x 128(t) tile, 256 threads, 8x8 microtile via f32x2 pairs on t.
// Double-buffered smem: 1 barrier per 8-k tile, stores overlap compute.
// ============================================================
__global__ void __launch_bounds__(256, 2) gemm_kernel(const float* __restrict__ x,
                                                      const float* __restrict__ Min) {
    const int cbase = blockIdx.x * 128;
    const int tbase = blockIdx.y * 128;
    const int b     = blockIdx.z / KSPLIT;
    const int ks    = blockIdx.z % KSPLIT;
    const int kbase = ks * KSEG;

    __shared__ float As[2][8][132];  // As[buf][k][c]
    __shared__ float Bs[2][8][132];  // Bs[buf][k][t]

    const int tid = threadIdx.x;
    const int a_k = tid >> 5;
    const int a_c = (tid & 31) << 2;
    const int b_t = tid >> 1;
    const int b_k = (tid & 1) << 2;
    const int tx = tid & 15;   // t microtile
    const int ty = tid >> 4;   // c microtile

    const float* Ap = Min + (size_t)(kbase + a_k) * D + cbase + a_c;
    const float* Bp = x + ((size_t)b * T + tbase + b_t) * D + kbase + b_k;

    ull acc[8][4];
#pragma unroll
    for (int i = 0; i < 8; i++)
#pragma unroll
        for (int j = 0; j < 4; j++) acc[i][j] = 0ull;

    // prologue: fill buffer 0
    {
        float4 av = *(const float4*)Ap;
        float4 bv = *(const float4*)Bp;
        *(float4*)&As[0][a_k][a_c] = av;
        Bs[0][b_k + 0][b_t] = bv.x;
        Bs[0][b_k + 1][b_t] = bv.y;
        Bs[0][b_k + 2][b_t] = bv.z;
        Bs[0][b_k + 3][b_t] = bv.w;
    }
    __syncthreads();

#pragma unroll 2
    for (int kt = 0; kt < KSEG / 8; kt++) {
        const int cur = kt & 1;
        float4 av, bv;
        const bool more = (kt + 1 < KSEG / 8);
        if (more) {
            Ap += 8 * D;
            Bp += 8;
            av = *(const float4*)Ap;
            bv = *(const float4*)Bp;
        }
#pragma unroll
        for (int kk = 0; kk < 8; kk++) {
            float4 af0 = *(const float4*)&As[cur][kk][ty * 8];
            float4 af1 = *(const float4*)&As[cur][kk][ty * 8 + 4];
            ull b20 = *(const ull*)&Bs[cur][kk][tx * 8];
            ull b21 = *(const ull*)&Bs[cur][kk][tx * 8 + 2];
            ull b22 = *(const ull*)&Bs[cur][kk][tx * 8 + 4];
            ull b23 = *(const ull*)&Bs[cur][kk][tx * 8 + 6];
            float a[8] = {af0.x, af0.y, af0.z, af0.w, af1.x, af1.y, af1.z, af1.w};
#pragma unroll
            for (int i = 0; i < 8; i++) {
                ull ai = pack2(a[i], a[i]);
                acc[i][0] = ffma2(ai, b20, acc[i][0]);
                acc[i][1] = ffma2(ai, b21, acc[i][1]);
                acc[i][2] = ffma2(ai, b22, acc[i][2]);
                acc[i][3] = ffma2(ai, b23, acc[i][3]);
            }
        }
        if (more) {
            const int nxt = cur ^ 1;
            *(float4*)&As[nxt][a_k][a_c] = av;
            Bs[nxt][b_k + 0][b_t] = bv.x;
            Bs[nxt][b_k + 1][b_t] = bv.y;
            Bs[nxt][b_k + 2][b_t] = bv.z;
            Bs[nxt][b_k + 3][b_t] = bv.w;
            __syncthreads();
        }
    }

    float* outbase = g_xp + (size_t)ks * ROWS * T;
#pragma unroll
    for (int i = 0; i < 8; i++) {
        int row = b * D + cbase + ty * 8 + i;
        float* dst = outbase + (size_t)row * T + tbase + tx * 8;
        float2 p0 = unpack2(acc[i][0]);
        float2 p1 = unpack2(acc[i][1]);
        float2 p2 = unpack2(acc[i][2]);
        float2 p3 = unpack2(acc[i][3]);
        *(float4*)dst       = make_float4(p0.x, p0.y, p1.x, p1.y);
        *(float4*)(dst + 4) = make_float4(p2.x, p2.y, p3.x, p3.y);
    }
}

// ============================================================
// Fused scan: W computed inline (prep_w folded in), recurrence + readout in
// f32x2, per-32-step smem transpose-reduce, output staged in smem and
// written coalesced to d_out (b,t,c) on the bf16 grid (transpose folded in).
// 8 warps/CTA = 8 consecutive c rows of one batch. Grid = 192.
// ============================================================
constexpr int SW = 8;

__global__ void __launch_bounds__(SW * 32) scan_kernel(const float* __restrict__ Ain,
                                                       const float* __restrict__ BC,
                                                       const float* __restrict__ Mfil,
                                                       float* __restrict__ out) {
    __shared__ float sx[SW][32];
    __shared__ float sp[SW][32 * 33];
    __shared__ float ys[2][32][9];   // [buf][t][cwarp], pitch 9 conflict-free

    const int tid = threadIdx.x;
    const int warp = tid >> 5;
    const int lane = tid & 31;
    const int row = blockIdx.x * SW + warp;  // 0..1535 (all 8 rows same batch)
    const int b = row / D;
    const int c = row % D;
    const int c0 = (blockIdx.x * SW) % D;

    // ---- A decay pairs: lane owns states {2l,2l+1} and {64+2l,64+2l+1} ----
    ull A20 = *(const ull*)(Ain + 2 * lane);
    ull A21 = *(const ull*)(Ain + 64 + 2 * lane);

    // ---- inline prep_w: W[s,c] = sum_k (BC[s,k]+BC[s,k+24]) * Mfil[k,c] ----
    float w0 = 0.f, w1 = 0.f, w2 = 0.f, w3 = 0.f;
    {
        const int s0 = 2 * lane, s2 = 64 + 2 * lane;
        const float* bc0 = BC + s0 * 2 * HALF;
        const float* bc1 = BC + (s0 + 1) * 2 * HALF;
        const float* bc2 = BC + s2 * 2 * HALF;
        const float* bc3 = BC + (s2 + 1) * 2 * HALF;
#pragma unroll
        for (int k = 0; k < HALF; k++) {
            float mf = Mfil[k * D + c];  // lane-invariant: broadcast
            w0 = fmaf(bc0[k] + bc0[HALF + k], mf, w0);
            w1 = fmaf(bc1[k] + bc1[HALF + k], mf, w1);
            w2 = fmaf(bc2[k] + bc2[HALF + k], mf, w2);
            w3 = fmaf(bc3[k] + bc3[HALF + k], mf, w3);
        }
    }
    ull W20 = pack2(w0, w1);
    ull W21 = pack2(w2, w3);

    const float* x0 = g_xp + (size_t)row * T;
    const float* x1 = x0 + (size_t)ROWS * T;
    const float* x2 = x1 + (size_t)ROWS * T;

    float* sxm = sx[warp];
    float* spm = sp[warp];

    ull h0 = 0ull, h1 = 0ull;

    float xv = x0[lane] + x1[lane] + x2[lane];  // sum K-split partials
    for (int t0 = 0; t0 < T; t0 += 32) {
        sxm[lane] = xv;
        __syncwarp();
        if (t0 + 32 < T) {  // prefetch next block (coalesced)
            int t = t0 + 32 + lane;
            xv = x0[t] + x1[t] + x2[t];
        }
#pragma unroll
        for (int tt = 0; tt < 32; tt++) {
            float xs = sxm[tt];
            ull xx = pack2(xs, xs);
            h0 = ffma2(A20, h0, xx);
            h1 = ffma2(A21, h1, xx);
            ull p = fmul2(h0, W20);
            p = ffma2(h1, W21, p);
            float2 pf = unpack2(p);
            spm[tt * 33 + lane] = pf.x + pf.y;  // conflict-free
        }
        __syncwarp();
        // lane j reduces time index j over the 32 source lanes
        const float* col = spm + lane * 33;
        float a0 = 0.f, a1 = 0.f, a2 = 0.f, a3 = 0.f;
#pragma unroll
        for (int l = 0; l < 32; l += 4) {
            a0 += col[l];
            a1 += col[l + 1];
            a2 += col[l + 2];
            a3 += col[l + 3];
        }
        const int buf = (t0 >> 5) & 1;
        ys[buf][lane][warp] = (a0 + a1) + (a2 + a3);
        __syncthreads();
        // cooperative coalesced write: thread -> (t = t0 + tid/8, c = c0 + tid%8)
        const int tt = tid >> 3, ci = tid & 7;
        float v = ys[buf][tt][ci];
        out[((size_t)b * T + t0 + tt) * D + c0 + ci] =
            __bfloat162float(__float2bfloat16(v));
    }
}

// ============================================================
extern "C" void kernel_launch(void* const* d_in, const int* in_sizes, int n_in,
                              void* d_out, int out_size) {
    const float* x = nullptr;
    const float *Min = nullptr, *Mfil = nullptr, *A = nullptr, *BC = nullptr;
    for (int i = 0; i < n_in; i++) {
        switch (in_sizes[i]) {  // all five element counts are distinct
            case B * T * D:     x    = (const float*)d_in[i]; break;  // 1572864
            case D * D:         Min  = (const float*)d_in[i]; break;  // 589824
            case HALF * D:      Mfil = (const float*)d_in[i]; break;  // 18432
            case S:             A    = (const float*)d_in[i]; break;  // 128
            case S * 2 * HALF:  BC   = (const float*)d_in[i]; break;  // 6144
        }
    }

    gemm_kernel<<<dim3(D / 128, T / 128, B * KSPLIT), 256>>>(x, Min);
    scan_kernel<<<ROWS / SW, SW * 32>>>(A, BC, Mfil, (float*)d_out);
}